// round 2
// baseline (speedup 1.0000x reference)
#include <cuda_runtime.h>
#include <cstdint>

// Problem constants (fixed by the reference setup)
#define EN 8192
#define EL 8192
#define DD 256
#define NG 64
#define SLOTS 16   // max label/node groups spanned by a 128-wide tile (fast path)

// ---------------- scratch (device globals; no allocation allowed) -----------
__device__ float    g_efn[EN * DD];
__device__ float    g_efl[EL * DD];
__device__ float    g_na[EN];
__device__ float    g_nb[EL];
__device__ unsigned g_rowmin[EN * NG];   // min over j in label group g of (nb_j - 2 dot)
__device__ unsigned g_colmin[NG * EL];   // min over i in node  group g of (na_i - 2 dot)
__device__ float    g_outn[NG * NG];

// Order-preserving float <-> uint encoding (unsigned ascending == float ascending)
__device__ __forceinline__ unsigned encf(float f) {
    unsigned u = __float_as_uint(f);
    return (u & 0x80000000u) ? ~u : (u | 0x80000000u);
}
__device__ __forceinline__ float decf(unsigned k) {
    unsigned u = (k & 0x80000000u) ? (k & 0x7FFFFFFFu) : ~k;
    return __uint_as_float(u);
}

#define SENTINEL 0xFFFFFFFFu
#define INF_F __int_as_float(0x7f800000)

// ---------------- kernel 0: reset the min buffers ---------------------------
__global__ void init_mins_kernel() {
    int i = blockIdx.x * blockDim.x + threadIdx.x;
    if (i < EN * NG) {
        g_rowmin[i] = SENTINEL;
        g_colmin[i] = SENTINEL;
    }
}

// ---------------- kernel 1: ef = (h[e0]+h[e1])*0.5 and row norms ------------
__global__ void build_ef_kernel(const float* __restrict__ h,
                                const int* __restrict__ edge,
                                int which /*0 = node, 1 = label*/) {
    float* ef  = which ? g_efl : g_efn;
    float* nrm = which ? g_nb  : g_na;
    const int E = EN;  // == EL
    int e = blockIdx.x;
    int t = threadIdx.x;  // 256 threads, t == feature index
    int i0 = edge[e];
    int i1 = edge[E + e];
    float v = 0.5f * (h[(size_t)i0 * DD + t] + h[(size_t)i1 * DD + t]);
    ef[(size_t)e * DD + t] = v;
    float s = v * v;
    #pragma unroll
    for (int o = 16; o > 0; o >>= 1) s += __shfl_down_sync(0xffffffffu, s, o);
    __shared__ float ws[8];
    if ((t & 31) == 0) ws[t >> 5] = s;
    __syncthreads();
    if (t < 8) {
        float x = ws[t];
        #pragma unroll
        for (int o = 4; o > 0; o >>= 1) x += __shfl_down_sync(0xffu, x, o);
        if (t == 0) nrm[e] = x;
    }
}

// ---------------- kernel 2: fused GEMM + group-min epilogue -----------------
// C tile 128x128, 256 threads, 8x8 register microtile, K = 256 in steps of 8,
// double-buffered shared tiles.
__global__ void __launch_bounds__(256)
gemm_min_kernel(const int* __restrict__ nbatch,
                const int* __restrict__ lbatch) {
    __shared__ float As[2][8][128];
    __shared__ float Bs[2][8][128];
    __shared__ int   gnc[128];           // node group per tile row
    __shared__ int   glc[128];           // label group per tile col
    __shared__ unsigned rm[128][SLOTS];  // row-side staging: [row][g - gl_lo]
    __shared__ unsigned cm[128][SLOTS];  // col-side staging: [col][g - gn_lo]

    const int tid   = threadIdx.x;
    const int tileI = blockIdx.y * 128;
    const int tileJ = blockIdx.x * 128;

    const int tx = tid & 15;   // col block 0..15
    const int ty = tid >> 4;   // row block 0..15

    // ---- global load mapping: one float4 of A and one of B per thread/stage
    const int lr = tid >> 1;          // 0..127
    const int lq = (tid & 1) * 4;     // k sub-offset 0 or 4
    const float* Aptr = &g_efn[(size_t)(tileI + lr) * DD + lq];
    const float* Bptr = &g_efl[(size_t)(tileJ + lr) * DD + lq];

    float c[8][8];
    #pragma unroll
    for (int i = 0; i < 8; i++)
        #pragma unroll
        for (int j = 0; j < 8; j++) c[i][j] = 0.f;

    // stage 0
    {
        float4 av = __ldg((const float4*)Aptr);
        float4 bv = __ldg((const float4*)Bptr);
        As[0][lq + 0][lr] = av.x; As[0][lq + 1][lr] = av.y;
        As[0][lq + 2][lr] = av.z; As[0][lq + 3][lr] = av.w;
        Bs[0][lq + 0][lr] = bv.x; Bs[0][lq + 1][lr] = bv.y;
        Bs[0][lq + 2][lr] = bv.z; Bs[0][lq + 3][lr] = bv.w;
    }
    // init epilogue staging + group arrays while waiting
    #pragma unroll 4
    for (int x = tid; x < 128 * SLOTS; x += 256) {
        ((unsigned*)rm)[x] = SENTINEL;
        ((unsigned*)cm)[x] = SENTINEL;
    }
    if (tid < 128) {
        gnc[tid] = nbatch[tileI + tid];
        glc[tid] = lbatch[tileJ + tid];
    }
    __syncthreads();

    const int NSTAGE = DD / 8;  // 32
    for (int s = 0; s < NSTAGE; ++s) {
        int cur = s & 1;
        float4 av2, bv2;
        if (s < NSTAGE - 1) {
            av2 = __ldg((const float4*)(Aptr + (s + 1) * 8));
            bv2 = __ldg((const float4*)(Bptr + (s + 1) * 8));
        }
        #pragma unroll
        for (int k = 0; k < 8; ++k) {
            float a0[8], b0[8];
            *(float4*)&a0[0] = *(const float4*)&As[cur][k][ty * 8];
            *(float4*)&a0[4] = *(const float4*)&As[cur][k][ty * 8 + 4];
            *(float4*)&b0[0] = *(const float4*)&Bs[cur][k][tx * 8];
            *(float4*)&b0[4] = *(const float4*)&Bs[cur][k][tx * 8 + 4];
            #pragma unroll
            for (int ii = 0; ii < 8; ++ii)
                #pragma unroll
                for (int jj = 0; jj < 8; ++jj)
                    c[ii][jj] = fmaf(a0[ii], b0[jj], c[ii][jj]);
        }
        if (s < NSTAGE - 1) {
            int nxt = cur ^ 1;
            As[nxt][lq + 0][lr] = av2.x; As[nxt][lq + 1][lr] = av2.y;
            As[nxt][lq + 2][lr] = av2.z; As[nxt][lq + 3][lr] = av2.w;
            Bs[nxt][lq + 0][lr] = bv2.x; Bs[nxt][lq + 1][lr] = bv2.y;
            Bs[nxt][lq + 2][lr] = bv2.z; Bs[nxt][lq + 3][lr] = bv2.w;
        }
        __syncthreads();
    }

    // ---------------- fused epilogue: group-min reductions ------------------
    const int gl_lo = glc[0], gl_hi = glc[127];
    const int gn_lo = gnc[0], gn_hi = gnc[127];
    const bool fastL = (gl_hi - gl_lo) < SLOTS;
    const bool fastN = (gn_hi - gn_lo) < SLOTS;
    const int row0 = ty * 8, col0 = tx * 8;

    float nav[8], nbv[8];
    #pragma unroll
    for (int ii = 0; ii < 8; ++ii) nav[ii] = g_na[tileI + row0 + ii];
    #pragma unroll
    for (int jj = 0; jj < 8; ++jj) nbv[jj] = g_nb[tileJ + col0 + jj];

    float cb[8];       // col-side running mins (per local col) for current gn run
    int curgn = -1;
    #pragma unroll
    for (int jj = 0; jj < 8; ++jj) cb[jj] = INF_F;

    #pragma unroll
    for (int ii = 0; ii < 8; ++ii) {
        int gi = gnc[row0 + ii];
        if (gi != curgn) {
            if (curgn >= 0) {
                #pragma unroll
                for (int jj = 0; jj < 8; ++jj) {
                    unsigned k = encf(cb[jj]);
                    if (fastN) atomicMin(&cm[col0 + jj][curgn - gn_lo], k);
                    else       atomicMin(&g_colmin[(size_t)curgn * EL + tileJ + col0 + jj], k);
                    cb[jj] = INF_F;
                }
            }
            curgn = gi;
        }
        int curgl = -1;
        float rbest = INF_F;
        #pragma unroll
        for (int jj = 0; jj < 8; ++jj) {
            float t2 = -2.0f * c[ii][jj];
            cb[jj] = fminf(cb[jj], t2 + nav[ii]);
            float rv = t2 + nbv[jj];
            int g = glc[col0 + jj];
            if (g != curgl) {
                if (curgl >= 0) {
                    unsigned k = encf(rbest);
                    if (fastL) atomicMin(&rm[row0 + ii][curgl - gl_lo], k);
                    else       atomicMin(&g_rowmin[(size_t)(tileI + row0 + ii) * NG + curgl], k);
                }
                curgl = g; rbest = rv;
            } else {
                rbest = fminf(rbest, rv);
            }
        }
        {
            unsigned k = encf(rbest);
            if (fastL) atomicMin(&rm[row0 + ii][curgl - gl_lo], k);
            else       atomicMin(&g_rowmin[(size_t)(tileI + row0 + ii) * NG + curgl], k);
        }
    }
    {
        #pragma unroll
        for (int jj = 0; jj < 8; ++jj) {
            unsigned k = encf(cb[jj]);
            if (fastN) atomicMin(&cm[col0 + jj][curgn - gn_lo], k);
            else       atomicMin(&g_colmin[(size_t)curgn * EL + tileJ + col0 + jj], k);
        }
    }
    __syncthreads();

    // flush shared staging to global
    if (fastL) {
        for (int x = tid; x < 128 * SLOTS; x += 256) {
            int r = x >> 4, sl = x & (SLOTS - 1);
            unsigned k = rm[r][sl];
            if (k != SENTINEL)
                atomicMin(&g_rowmin[(size_t)(tileI + r) * NG + gl_lo + sl], k);
        }
    }
    if (fastN) {
        for (int x = tid; x < 128 * SLOTS; x += 256) {
            int cc = x >> 4, sl = x & (SLOTS - 1);
            unsigned k = cm[cc][sl];
            if (k != SENTINEL)
                atomicMin(&g_colmin[(size_t)(gn_lo + sl) * EL + tileJ + cc], k);
        }
    }
}

// ---------------- kernel 3: row side -> out_n = seg_mean over node groups ---
__global__ void finalize_row_kernel(const int* __restrict__ nbatch) {
    int gl = blockIdx.x;
    __shared__ float ssum[NG];
    __shared__ int   scnt[NG];
    int t = threadIdx.x;
    if (t < NG) { ssum[t] = 0.f; scnt[t] = 0; }
    __syncthreads();
    for (int i = t; i < EN; i += blockDim.x) {
        unsigned k = g_rowmin[(size_t)i * NG + gl];
        float val = 0.f;
        if (k != SENTINEL) val = -sqrtf(fmaxf(g_na[i] + decf(k), 0.f));
        int gn = nbatch[i];
        int gn0 = __shfl_sync(0xffffffffu, gn, 0);
        if (__all_sync(0xffffffffu, gn == gn0)) {   // sorted groups: common case
            #pragma unroll
            for (int o = 16; o > 0; o >>= 1) val += __shfl_down_sync(0xffffffffu, val, o);
            if ((t & 31) == 0) { atomicAdd(&ssum[gn0], val); atomicAdd(&scnt[gn0], 32); }
        } else {
            atomicAdd(&ssum[gn], val); atomicAdd(&scnt[gn], 1);
        }
    }
    __syncthreads();
    if (t < NG) g_outn[(size_t)t * NG + gl] = ssum[t] / (float)max(scnt[t], 1);
}

// ---------------- kernel 4: col side + combine -> d_out ---------------------
__global__ void finalize_col_kernel(const int* __restrict__ lbatch,
                                    float* __restrict__ out) {
    int gn = blockIdx.x;
    __shared__ float ssum[NG];
    __shared__ int   scnt[NG];
    int t = threadIdx.x;
    if (t < NG) { ssum[t] = 0.f; scnt[t] = 0; }
    __syncthreads();
    for (int j = t; j < EL; j += blockDim.x) {
        unsigned k = g_colmin[(size_t)gn * EL + j];
        float val = 0.f;
        if (k != SENTINEL) val = -sqrtf(fmaxf(g_nb[j] + decf(k), 0.f));
        int gl = lbatch[j];
        int gl0 = __shfl_sync(0xffffffffu, gl, 0);
        if (__all_sync(0xffffffffu, gl == gl0)) {
            #pragma unroll
            for (int o = 16; o > 0; o >>= 1) val += __shfl_down_sync(0xffffffffu, val, o);
            if ((t & 31) == 0) { atomicAdd(&ssum[gl0], val); atomicAdd(&scnt[gl0], 32); }
        } else {
            atomicAdd(&ssum[gl], val); atomicAdd(&scnt[gl], 1);
        }
    }
    __syncthreads();
    if (t < NG) {
        float out_l = ssum[t] / (float)max(scnt[t], 1);
        out[(size_t)gn * NG + t] = 0.5f * (g_outn[(size_t)gn * NG + t] + out_l);
    }
}

// ---------------- launch ----------------------------------------------------
extern "C" void kernel_launch(void* const* d_in, const int* in_sizes, int n_in,
                              void* d_out, int out_size) {
    const float* h           = (const float*)d_in[0];
    const int*   node_edge   = (const int*)d_in[1];
    const int*   node_batch  = (const int*)d_in[2];
    const int*   label_edge  = (const int*)d_in[3];
    const int*   label_batch = (const int*)d_in[4];
    float* out = (float*)d_out;

    init_mins_kernel<<<(EN * NG + 255) / 256, 256>>>();
    build_ef_kernel<<<EN, 256>>>(h, node_edge, 0);
    build_ef_kernel<<<EL, 256>>>(h, label_edge, 1);
    gemm_min_kernel<<<dim3(EL / 128, EN / 128), 256>>>(node_batch, label_batch);
    finalize_row_kernel<<<NG, 256>>>(node_batch);
    finalize_col_kernel<<<NG, 256>>>(label_batch, out);
}

// round 3
// speedup vs baseline: 3.1709x; 3.1709x over previous
#include <cuda_runtime.h>
#include <cuda_bf16.h>
#include <cstdint>

#define EN 8192
#define EL 8192
#define DD 256
#define NG 64
#define SLOTS 16

// ---------------- scratch (device globals) ----------------------------------
__device__ __nv_bfloat16 g_efn_bf[EN * DD];
__device__ __nv_bfloat16 g_efl_bf[EL * DD];
__device__ float    g_na[EN];
__device__ float    g_nb[EL];
__device__ unsigned g_rowmin[EN * NG];
__device__ unsigned g_colmin[NG * EL];
__device__ float    g_outn[NG * NG];

__device__ __forceinline__ unsigned encf(float f) {
    unsigned u = __float_as_uint(f);
    return (u & 0x80000000u) ? ~u : (u | 0x80000000u);
}
__device__ __forceinline__ float decf(unsigned k) {
    unsigned u = (k & 0x80000000u) ? (k & 0x7FFFFFFFu) : ~k;
    return __uint_as_float(u);
}

#define SENTINEL 0xFFFFFFFFu
#define INF_F __int_as_float(0x7f800000)

// ---------------- kernel 0: reset min buffers -------------------------------
__global__ void init_mins_kernel() {
    int i = blockIdx.x * blockDim.x + threadIdx.x;
    if (i < EN * NG) {
        g_rowmin[i] = SENTINEL;
        g_colmin[i] = SENTINEL;
    }
}

// ---------------- kernel 1: ef = (h[e0]+h[e1])*0.5 (bf16) + fp32 norms ------
__global__ void build_ef_kernel(const float* __restrict__ h,
                                const int* __restrict__ edge,
                                int which) {
    __nv_bfloat16* ef = which ? g_efl_bf : g_efn_bf;
    float* nrm        = which ? g_nb     : g_na;
    int e = blockIdx.x;
    int t = threadIdx.x;  // 256 threads == feature dim
    int i0 = edge[e];
    int i1 = edge[EN + e];
    float v = 0.5f * (h[(size_t)i0 * DD + t] + h[(size_t)i1 * DD + t]);
    ef[(size_t)e * DD + t] = __float2bfloat16_rn(v);
    float s = v * v;
    #pragma unroll
    for (int o = 16; o > 0; o >>= 1) s += __shfl_down_sync(0xffffffffu, s, o);
    __shared__ float ws[8];
    if ((t & 31) == 0) ws[t >> 5] = s;
    __syncthreads();
    if (t < 8) {
        float x = ws[t];
        #pragma unroll
        for (int o = 4; o > 0; o >>= 1) x += __shfl_down_sync(0xffu, x, o);
        if (t == 0) nrm[e] = x;
    }
}

// ---------------- PTX helpers -----------------------------------------------
__device__ __forceinline__ void cp16(uint32_t dst, const void* src) {
    asm volatile("cp.async.cg.shared.global [%0], [%1], 16;" :: "r"(dst), "l"(src));
}
__device__ __forceinline__ void cp_commit() {
    asm volatile("cp.async.commit_group;");
}
__device__ __forceinline__ void cp_wait0() {
    asm volatile("cp.async.wait_group 0;");
}
__device__ __forceinline__ void ldmx4(uint32_t* r, uint32_t addr) {
    asm volatile("ldmatrix.sync.aligned.m8n8.x4.shared.b16 {%0,%1,%2,%3}, [%4];"
                 : "=r"(r[0]), "=r"(r[1]), "=r"(r[2]), "=r"(r[3]) : "r"(addr));
}
__device__ __forceinline__ void mma16816(float* d, const uint32_t* a,
                                         uint32_t b0, uint32_t b1) {
    asm volatile("mma.sync.aligned.m16n8k16.row.col.f32.bf16.bf16.f32 "
                 "{%0,%1,%2,%3}, {%4,%5,%6,%7}, {%8,%9}, {%0,%1,%2,%3};"
                 : "+f"(d[0]), "+f"(d[1]), "+f"(d[2]), "+f"(d[3])
                 : "r"(a[0]), "r"(a[1]), "r"(a[2]), "r"(a[3]), "r"(b0), "r"(b1));
}

// ---------------- kernel 2: bf16 MMA GEMM + fused group-min epilogue --------
// CTA tile 128x128, 8 warps (2x4), warp tile 64x32, BK=32, cp.async dbl-buffer.
#define LDA 40          // 32 + 8 pad (bf16 elems) -> conflict-free ldmatrix
#define STAGE_B (2 * 128 * LDA * 2)   // bytes per stage (A half + B half)
#define HALF_B  (128 * LDA * 2)

__global__ void __launch_bounds__(256)
gemm_bf16_min_kernel(const int* __restrict__ nbatch,
                     const int* __restrict__ lbatch) {
    __shared__ __align__(16) __nv_bfloat16 sAB[2][2][128 * LDA];  // 40960 B
    __shared__ int gnc[128];
    __shared__ int glc[128];

    const int tid   = threadIdx.x;
    const int tileI = blockIdx.y * 128;
    const int tileJ = blockIdx.x * 128;
    const int wid  = tid >> 5;
    const int lane = tid & 31;
    const int wr = wid & 1;          // 2 warp rows  (64 rows each)
    const int wc = wid >> 1;         // 4 warp cols  (32 cols each)
    const int wrBase = wr * 64;
    const int wcBase = wc * 32;

    const uint32_t smemBase = (uint32_t)__cvta_generic_to_shared(&sAB[0][0][0]);

    // ldmatrix lane address components
    const int aRow = (lane & 7) + ((lane >> 3) & 1) * 8;
    const int aK   = (lane >> 4) * 8;
    const int bRow = (lane & 7) + (lane >> 4) * 8;
    const int bK   = ((lane >> 3) & 1) * 8;

    // global->shared mapping (one half-row of 16 bf16, 2x cp.async 16B)
    const int ldRow = tid >> 1;
    const int ldKq  = (tid & 1) * 16;
    const __nv_bfloat16* gA = g_efn_bf + (size_t)(tileI + ldRow) * DD;
    const __nv_bfloat16* gB = g_efl_bf + (size_t)(tileJ + ldRow) * DD;
    const uint32_t dOffA = (uint32_t)(ldRow * LDA + ldKq) * 2;
    const uint32_t dOffB = HALF_B + dOffA;

    if (tid < 128) {
        gnc[tid] = nbatch[tileI + tid];
        glc[tid] = lbatch[tileJ + tid];
    }

    float c[4][4][4];
    #pragma unroll
    for (int mi = 0; mi < 4; mi++)
        #pragma unroll
        for (int ni = 0; ni < 4; ni++)
            #pragma unroll
            for (int q = 0; q < 4; q++) c[mi][ni][q] = 0.f;

    // prologue: stage 0
    {
        uint32_t st = smemBase;
        cp16(st + dOffA,      gA + ldKq);
        cp16(st + dOffA + 16, gA + ldKq + 8);
        cp16(st + dOffB,      gB + ldKq);
        cp16(st + dOffB + 16, gB + ldKq + 8);
        cp_commit();
    }

    const int NS = DD / 32;  // 8 stages
    for (int s = 0; s < NS; ++s) {
        cp_wait0();
        __syncthreads();
        if (s + 1 < NS) {
            uint32_t st = smemBase + ((s + 1) & 1) * STAGE_B;
            int ko = (s + 1) * 32;
            cp16(st + dOffA,      gA + ko + ldKq);
            cp16(st + dOffA + 16, gA + ko + ldKq + 8);
            cp16(st + dOffB,      gB + ko + ldKq);
            cp16(st + dOffB + 16, gB + ko + ldKq + 8);
            cp_commit();
        }
        uint32_t sA = smemBase + (s & 1) * STAGE_B;
        uint32_t sB = sA + HALF_B;
        #pragma unroll
        for (int kb = 0; kb < 32; kb += 16) {
            uint32_t a[4][4];
            #pragma unroll
            for (int mi = 0; mi < 4; mi++)
                ldmx4(a[mi], sA + (uint32_t)((wrBase + mi * 16 + aRow) * LDA + kb + aK) * 2);
            uint32_t b[2][4];
            #pragma unroll
            for (int nq = 0; nq < 2; nq++)
                ldmx4(b[nq], sB + (uint32_t)((wcBase + nq * 16 + bRow) * LDA + kb + bK) * 2);
            #pragma unroll
            for (int mi = 0; mi < 4; mi++) {
                #pragma unroll
                for (int nq = 0; nq < 2; nq++) {
                    mma16816(c[mi][nq * 2 + 0], a[mi], b[nq][0], b[nq][1]);
                    mma16816(c[mi][nq * 2 + 1], a[mi], b[nq][2], b[nq][3]);
                }
            }
        }
    }
    __syncthreads();

    // -------- epilogue: overlay staging on the A/B smem, group-min reduce ---
    unsigned* stag = (unsigned*)&sAB[0][0][0];
    for (int x = tid; x < 128 * SLOTS * 2; x += 256) stag[x] = SENTINEL;
    __syncthreads();
    unsigned (*rm)[SLOTS] = (unsigned(*)[SLOTS])stag;                 // [row][slot]
    unsigned (*cm)[SLOTS] = (unsigned(*)[SLOTS])(stag + 128 * SLOTS); // [col][slot]

    const int gl_lo = glc[0], gl_hi = glc[127];
    const int gn_lo = gnc[0], gn_hi = gnc[127];
    const bool fastL = (gl_hi - gl_lo) < SLOTS;
    const bool fastN = (gn_hi - gn_lo) < SLOTS;

    const int g  = lane >> 2;
    const int t2 = (lane & 3) * 2;

    int   lrows[8], grows[8], lcols[8], gcols[8];
    float nav[8], nbv[8];
    #pragma unroll
    for (int m = 0; m < 8; m++) {
        lrows[m] = wrBase + (m >> 1) * 16 + g + (m & 1) * 8;
        grows[m] = gnc[lrows[m]];
        nav[m]   = g_na[tileI + lrows[m]];
    }
    #pragma unroll
    for (int n = 0; n < 8; n++) {
        lcols[n] = wcBase + (n >> 1) * 8 + t2 + (n & 1);
        gcols[n] = glc[lcols[n]];
        nbv[n]   = g_nb[tileJ + lcols[n]];
    }

    // row-side: per owned row, min over owned cols per label-group run
    #pragma unroll
    for (int m = 0; m < 8; m++) {
        const int mi = m >> 1, h = m & 1;
        float rbest = INF_F;
        int curgl = -1;
        #pragma unroll
        for (int n = 0; n < 8; n++) {
            const int ni = n >> 1, u = n & 1;
            float rv = fmaf(-2.f, c[mi][ni][h * 2 + u], nbv[n]);
            int gg = gcols[n];
            if (gg != curgl) {
                if (curgl >= 0) {
                    unsigned k = encf(rbest);
                    if (fastL) atomicMin(&rm[lrows[m]][curgl - gl_lo], k);
                    else       atomicMin(&g_rowmin[(size_t)(tileI + lrows[m]) * NG + curgl], k);
                }
                curgl = gg; rbest = rv;
            } else {
                rbest = fminf(rbest, rv);
            }
        }
        unsigned k = encf(rbest);
        if (fastL) atomicMin(&rm[lrows[m]][curgl - gl_lo], k);
        else       atomicMin(&g_rowmin[(size_t)(tileI + lrows[m]) * NG + curgl], k);
    }

    // col-side: per owned col, min over owned rows per node-group run
    {
        float cb[8];
        #pragma unroll
        for (int n = 0; n < 8; n++) cb[n] = INF_F;
        int curgn = -1;
        #pragma unroll
        for (int m = 0; m < 8; m++) {
            const int mi = m >> 1, h = m & 1;
            int gi = grows[m];
            if (gi != curgn) {
                if (curgn >= 0) {
                    #pragma unroll
                    for (int n = 0; n < 8; n++) {
                        unsigned k = encf(cb[n]);
                        if (fastN) atomicMin(&cm[lcols[n]][curgn - gn_lo], k);
                        else       atomicMin(&g_colmin[(size_t)curgn * EL + tileJ + lcols[n]], k);
                        cb[n] = INF_F;
                    }
                }
                curgn = gi;
            }
            #pragma unroll
            for (int n = 0; n < 8; n++) {
                const int ni = n >> 1, u = n & 1;
                cb[n] = fminf(cb[n], fmaf(-2.f, c[mi][ni][h * 2 + u], nav[m]));
            }
        }
        #pragma unroll
        for (int n = 0; n < 8; n++) {
            unsigned k = encf(cb[n]);
            if (fastN) atomicMin(&cm[lcols[n]][curgn - gn_lo], k);
            else       atomicMin(&g_colmin[(size_t)curgn * EL + tileJ + lcols[n]], k);
        }
    }
    __syncthreads();

    // flush shared staging to global
    if (fastL) {
        for (int x = tid; x < 128 * SLOTS; x += 256) {
            int r = x >> 4, sl = x & (SLOTS - 1);
            unsigned k = rm[r][sl];
            if (k != SENTINEL)
                atomicMin(&g_rowmin[(size_t)(tileI + r) * NG + gl_lo + sl], k);
        }
    }
    if (fastN) {
        for (int x = tid; x < 128 * SLOTS; x += 256) {
            int cc = x >> 4, sl = x & (SLOTS - 1);
            unsigned k = cm[cc][sl];
            if (k != SENTINEL)
                atomicMin(&g_colmin[(size_t)(gn_lo + sl) * EL + tileJ + cc], k);
        }
    }
}

// ---------------- kernel 3: row side -> out_n -------------------------------
__global__ void finalize_row_kernel(const int* __restrict__ nbatch) {
    int gl = blockIdx.x;
    __shared__ float ssum[NG];
    __shared__ int   scnt[NG];
    int t = threadIdx.x;
    if (t < NG) { ssum[t] = 0.f; scnt[t] = 0; }
    __syncthreads();
    for (int i = t; i < EN; i += blockDim.x) {
        unsigned k = g_rowmin[(size_t)i * NG + gl];
        float val = 0.f;
        if (k != SENTINEL) val = -sqrtf(fmaxf(g_na[i] + decf(k), 0.f));
        int gn = nbatch[i];
        int gn0 = __shfl_sync(0xffffffffu, gn, 0);
        if (__all_sync(0xffffffffu, gn == gn0)) {
            #pragma unroll
            for (int o = 16; o > 0; o >>= 1) val += __shfl_down_sync(0xffffffffu, val, o);
            if ((t & 31) == 0) { atomicAdd(&ssum[gn0], val); atomicAdd(&scnt[gn0], 32); }
        } else {
            atomicAdd(&ssum[gn], val); atomicAdd(&scnt[gn], 1);
        }
    }
    __syncthreads();
    if (t < NG) g_outn[(size_t)t * NG + gl] = ssum[t] / (float)max(scnt[t], 1);
}

// ---------------- kernel 4: col side + combine ------------------------------
__global__ void finalize_col_kernel(const int* __restrict__ lbatch,
                                    float* __restrict__ out) {
    int gn = blockIdx.x;
    __shared__ float ssum[NG];
    __shared__ int   scnt[NG];
    int t = threadIdx.x;
    if (t < NG) { ssum[t] = 0.f; scnt[t] = 0; }
    __syncthreads();
    for (int j = t; j < EL; j += blockDim.x) {
        unsigned k = g_colmin[(size_t)gn * EL + j];
        float val = 0.f;
        if (k != SENTINEL) val = -sqrtf(fmaxf(g_nb[j] + decf(k), 0.f));
        int gl = lbatch[j];
        int gl0 = __shfl_sync(0xffffffffu, gl, 0);
        if (__all_sync(0xffffffffu, gl == gl0)) {
            #pragma unroll
            for (int o = 16; o > 0; o >>= 1) val += __shfl_down_sync(0xffffffffu, val, o);
            if ((t & 31) == 0) { atomicAdd(&ssum[gl0], val); atomicAdd(&scnt[gl0], 32); }
        } else {
            atomicAdd(&ssum[gl], val); atomicAdd(&scnt[gl], 1);
        }
    }
    __syncthreads();
    if (t < NG) {
        float out_l = ssum[t] / (float)max(scnt[t], 1);
        out[(size_t)gn * NG + t] = 0.5f * (g_outn[(size_t)gn * NG + t] + out_l);
    }
}

// ---------------- launch ----------------------------------------------------
extern "C" void kernel_launch(void* const* d_in, const int* in_sizes, int n_in,
                              void* d_out, int out_size) {
    const float* h           = (const float*)d_in[0];
    const int*   node_edge   = (const int*)d_in[1];
    const int*   node_batch  = (const int*)d_in[2];
    const int*   label_edge  = (const int*)d_in[3];
    const int*   label_batch = (const int*)d_in[4];
    float* out = (float*)d_out;

    init_mins_kernel<<<(EN * NG + 255) / 256, 256>>>();
    build_ef_kernel<<<EN, 256>>>(h, node_edge, 0);
    build_ef_kernel<<<EL, 256>>>(h, label_edge, 1);
    gemm_bf16_min_kernel<<<dim3(EL / 128, EN / 128), 256>>>(node_batch, label_batch);
    finalize_row_kernel<<<NG, 256>>>(node_batch);
    finalize_col_kernel<<<NG, 256>>>(label_batch, out);
}